// round 10
// baseline (speedup 1.0000x reference)
#include <cuda_runtime.h>
#include <math_constants.h>

#define BSZ   64
#define NGEN  128
#define NCLS  30
#define SEQ   2048
#define G     16
#define TGOLD (BSZ * G)                              // 1024
#define COST_ELEMS ((size_t)BSZ * NGEN * TGOLD)      // 8388608
#define NITER 16                                     // 8 dists x 2 rows
#define NLSA  BSZ                                    // 64 lsa blocks (first)
#define BLOCKS_PER_EX 64                             // 128 rows / 2

struct Ptrs {
    const float* pos[8];   // 8 positional logit tensors [BSZ*NGEN, SEQ]
    const int*   gidx[8];  // 8 gold index arrays [TGOLD]
};

__device__ int g_cnt[BSZ];

__global__ void init_kernel() {
    if (threadIdx.x < BSZ) g_cnt[threadIdx.x] = 0;
}

// ---------------------------------------------------------------------------
// helpers
// ---------------------------------------------------------------------------
__device__ __forceinline__ unsigned smem_u32(const void* p) {
    unsigned a;
    asm("{ .reg .u64 t; cvta.to.shared.u64 t, %1; cvt.u32.u64 %0, t; }"
        : "=r"(a) : "l"(p));
    return a;
}
__device__ __forceinline__ void cp_async16(unsigned dst, const float* src) {
    asm volatile("cp.async.cg.shared.global [%0], [%1], 16;" :: "r"(dst), "l"(src));
}
__device__ __forceinline__ unsigned fkey(float x) {
    int b = __float_as_int(x);
    return (unsigned)(b ^ ((b >> 31) | 0x80000000));
}
__device__ __forceinline__ float funkey(unsigned k) {
    int b = (k & 0x80000000u) ? (int)(k ^ 0x80000000u) : (int)(~k);
    return __int_as_float(b);
}
__device__ __forceinline__ unsigned redux_min_u32(unsigned x) {
    unsigned r;
    asm volatile("redux.sync.min.u32 %0, %1, 0xffffffff;" : "=r"(r) : "r"(x));
    return r;
}

// ---------------------------------------------------------------------------
// Fused kernel.
//  bid <  64 : lsa role — resident from wave 1; warp 0 spins until its
//              example's 64 cost blocks are done, then solves LAPJV (f32,
//              register state, redux argmin — validated identical assignment
//              to the f64 reference). Overlaps the cost phase for nearly all
//              examples.
//  bid >= 64 : cost role — TWO (b,n) rows, depth-3 cp.async pipeline over 4
//              raw-logit stages, exp at use site, ONE barrier/iteration,
//              gold-index int4 loaded once per dist (identical arithmetic to
//              R9 -> bit-identical cost output). Then fence + counter bump.
// ---------------------------------------------------------------------------
__global__ __launch_bounds__(256)
void fused_kernel(const float* __restrict__ prel, const int* __restrict__ grel,
                  Ptrs ptrs, float* __restrict__ out) {
    __shared__ __align__(16) char smem_raw[33152];

    if (blockIdx.x >= NLSA) {
        // ========================= cost role =========================
        float (*stage)[SEQ] = (float (*)[SEQ])smem_raw;              // 32 KB
        float (*relp)[32]   = (float (*)[32])(smem_raw + 32768);     // 256 B
        float (*red)[8]     = (float (*)[8])(smem_raw + 33024);      // 64 B

        const int row0 = (blockIdx.x - NLSA) * 2;
        const int tid  = threadIdx.x;
        const int w    = tid >> 5;
        const int lane = tid & 31;

        const unsigned sbase = smem_u32(&stage[0][0]);

        // prologue: iterations 0..2
        #pragma unroll
        for (int k = 0; k < 3; k++) {
            const float* src = ptrs.pos[k >> 1] + (size_t)(row0 + (k & 1)) * SEQ;
            unsigned dst = sbase + (unsigned)((k & 3) * (SEQ * 4)) + (unsigned)(tid * 16);
            cp_async16(dst, src + 4 * tid);
            cp_async16(dst + 4096, src + 1024 + 4 * tid);
            asm volatile("cp.async.commit_group;");
        }

        // rel-class softmax: warp 0 -> row0, warp 1 -> row0+1
        if (tid < 64) {
            float e = (lane < NCLS) ? __expf(prel[(size_t)(row0 + w) * NCLS + lane]) : 0.f;
            float s = e;
            #pragma unroll
            for (int o = 16; o; o >>= 1) s += __shfl_xor_sync(0xffffffffu, s, o);
            if (lane < NCLS) relp[w][lane] = e / s;
        }
        __syncthreads();

        const int4 gr = ((const int4*)grel)[tid];
        float acc[2][4];
        #pragma unroll
        for (int r = 0; r < 2; r++) {
            acc[r][0] = relp[r][gr.x];
            acc[r][1] = relp[r][gr.y];
            acc[r][2] = relp[r][gr.z];
            acc[r][3] = relp[r][gr.w];
        }

        int4 gi;
        #pragma unroll
        for (int k = 0; k < NITER; k++) {
            const int d  = k >> 1;
            const int r  = k & 1;
            const int sb = k & 3;
            const int pb = k & 1;

            if (k <= 13)      asm volatile("cp.async.wait_group 2;");
            else if (k == 14) asm volatile("cp.async.wait_group 1;");
            else              asm volatile("cp.async.wait_group 0;");

            if (r == 0) gi = ((const int4*)ptrs.gidx[d])[tid];

            const float4* sp = (const float4*)&stage[sb][0];
            float4 x0 = sp[tid];
            float4 x1 = sp[tid + 256];
            float lsum = (__expf(x0.x) + __expf(x0.y)) + (__expf(x0.z) + __expf(x0.w))
                       + (__expf(x1.x) + __expf(x1.y)) + (__expf(x1.z) + __expf(x1.w));
            #pragma unroll
            for (int o = 16; o; o >>= 1) lsum += __shfl_xor_sync(0xffffffffu, lsum, o);
            if (lane == 0) red[pb][w] = lsum;
            __syncthreads();   // red visible; cp.asyncs of iter k published;
                               // gathers of k-1 ordered before k+3 refill

            float s = ((red[pb][0] + red[pb][1]) + (red[pb][2] + red[pb][3]))
                    + ((red[pb][4] + red[pb][5]) + (red[pb][6] + red[pb][7]));
            float inv = 1.0f / s;

            acc[r][0] += __expf(stage[sb][gi.x]) * inv;
            acc[r][1] += __expf(stage[sb][gi.y]) * inv;
            acc[r][2] += __expf(stage[sb][gi.z]) * inv;
            acc[r][3] += __expf(stage[sb][gi.w]) * inv;

            if (k + 3 < NITER) {
                const int kn = k + 3;
                const float* src = ptrs.pos[kn >> 1] + (size_t)(row0 + (kn & 1)) * SEQ;
                unsigned dst = sbase + (unsigned)((kn & 3) * (SEQ * 4))
                                     + (unsigned)(tid * 16);
                cp_async16(dst, src + 4 * tid);
                cp_async16(dst + 4096, src + 1024 + 4 * tid);
                asm volatile("cp.async.commit_group;");
            }
        }

        #pragma unroll
        for (int r = 0; r < 2; r++) {
            float4 res = make_float4(-acc[r][0], -acc[r][1], -acc[r][2], -acc[r][3]);
            ((float4*)(out + (size_t)(row0 + r) * TGOLD))[tid] = res;
        }

        __threadfence();
        __syncthreads();
        if (tid == 0) atomicAdd(&g_cnt[row0 >> 7], 1);

    } else {
        // ========================= lsa role =========================
        if (threadIdx.x >= 32) return;
        const int b = blockIdx.x;
        const int lane = threadIdx.x;

        float* Cf = (float*)smem_raw;                 // 8 KB
        int*   x  = (int*)(smem_raw + 8192);          // 64 B

        if (lane == 0) {
            while (atomicAdd(&g_cnt[b], 0) < BLOCKS_PER_EX) __nanosleep(128);
        }
        __syncwarp();
        __threadfence();

        const float* cost = out;
        for (int j = lane; j < NGEN; j += 32) {
            const float4* src = (const float4*)(cost + ((size_t)(b * NGEN + j)) * TGOLD + b * G);
            #pragma unroll
            for (int q = 0; q < 4; q++) {
                float4 f = src[q];
                Cf[(q * 4 + 0) * NGEN + j] = f.x;
                Cf[(q * 4 + 1) * NGEN + j] = f.y;
                Cf[(q * 4 + 2) * NGEN + j] = f.z;
                Cf[(q * 4 + 3) * NGEN + j] = f.w;
            }
        }
        __syncwarp();

        float vreg[4];                 // v[j], j = lane + 32*t (ZERO init)
        int   yreg[4];                 // col -> row (-1 free)
        #pragma unroll
        for (int t = 0; t < 4; t++) { vreg[t] = 0.f; yreg[t] = -1; }

        for (int f = 0; f < G; f++) {
            float dreg[4];
            int   pr[4];
            #pragma unroll
            for (int t = 0; t < 4; t++) {
                dreg[t] = Cf[f * NGEN + lane + 32 * t] - vreg[t];
                pr[t] = f;
            }
            unsigned scan = 0;
            int jmin;
            float mu;

            while (true) {
                unsigned bestk = 0xFFFFFFFFu;
                unsigned bestj = 0xFFFFFFFFu;
                #pragma unroll
                for (int t = 0; t < 4; t++) {
                    if (!((scan >> t) & 1u)) {
                        unsigned k = fkey(dreg[t]);
                        if (k < bestk) { bestk = k; bestj = (unsigned)(lane + 32 * t); }
                    }
                }
                unsigned kmin = redux_min_u32(bestk);
                unsigned j1   = redux_min_u32((bestk == kmin) ? bestj : 0xFFFFFFFFu);
                mu   = funkey(kmin);
                jmin = (int)j1;

                const int tt = jmin >> 5, sl = jmin & 31;
                if (sl == lane) scan |= 1u << tt;

                int   ysel = (tt == 0) ? yreg[0] : (tt == 1) ? yreg[1]
                           : (tt == 2) ? yreg[2] : yreg[3];
                float vsel = (tt == 0) ? vreg[0] : (tt == 1) ? vreg[1]
                           : (tt == 2) ? vreg[2] : vreg[3];
                int   i1 = __shfl_sync(0xffffffffu, ysel, sl);
                float vj = __shfl_sync(0xffffffffu, vsel, sl);
                if (i1 < 0) break;

                float ui = Cf[i1 * NGEN + jmin] - vj;

                #pragma unroll
                for (int t = 0; t < 4; t++) {
                    if (!((scan >> t) & 1u)) {
                        int j = lane + 32 * t;
                        float nd = mu + (Cf[i1 * NGEN + j] - vreg[t]) - ui;
                        if (nd < dreg[t]) { dreg[t] = nd; pr[t] = i1; }
                    }
                }
            }

            #pragma unroll
            for (int t = 0; t < 4; t++)
                if ((scan >> t) & 1u) vreg[t] += dreg[t] - mu;

            int j = jmin;
            while (true) {
                const int tt = j >> 5, sl = j & 31;
                int psel = (tt == 0) ? pr[0] : (tt == 1) ? pr[1]
                         : (tt == 2) ? pr[2] : pr[3];
                int i = __shfl_sync(0xffffffffu, psel, sl);
                if ((j & 31) == lane) yreg[j >> 5] = i;   // y[j] = i
                int jn = 0;
                if (lane == 0) {
                    jn = (i == f) ? -1 : x[i];
                    x[i] = j;
                }
                jn = __shfl_sync(0xffffffffu, jn, 0);
                if (i == f) break;
                j = jn;
            }
            __syncwarp();
        }

        // transposed return: col[i] = x[i]; order = argsort(col)
        if (lane < G) {
            float* rows_out = (float*)(out + COST_ELEMS);
            float* cols_out = rows_out + (size_t)BSZ * G;
            int c = x[lane];
            int rank = 0;
            #pragma unroll
            for (int r2 = 0; r2 < G; r2++) rank += (x[r2] < c) ? 1 : 0;
            rows_out[b * G + rank] = (float)c;
            cols_out[b * G + rank] = (float)lane;
        }
    }
}

// ---------------------------------------------------------------------------
// Launch
// ---------------------------------------------------------------------------
extern "C" void kernel_launch(void* const* d_in, const int* in_sizes, int n_in,
                              void* d_out, int out_size) {
    const float* prel = (const float*)d_in[0];
    Ptrs ptrs;
    for (int d = 0; d < 8; d++) ptrs.pos[d]  = (const float*)d_in[1 + d];
    const int* grel = (const int*)d_in[9];
    for (int d = 0; d < 8; d++) ptrs.gidx[d] = (const int*)d_in[10 + d];

    float* out = (float*)d_out;

    init_kernel<<<1, 64>>>();
    fused_kernel<<<NLSA + (BSZ * NGEN) / 2, 256>>>(prel, grel, ptrs, out);
}

// round 11
// speedup vs baseline: 1.2085x; 1.2085x over previous
#include <cuda_runtime.h>
#include <math_constants.h>

#define BSZ   64
#define NGEN  128
#define NCLS  30
#define SEQ   2048
#define G     16
#define TGOLD (BSZ * G)                              // 1024
#define COST_ELEMS ((size_t)BSZ * NGEN * TGOLD)      // 8388608
#define NITER 16                                     // 8 dists x 2 rows

struct Ptrs {
    const float* pos[8];   // 8 positional logit tensors [BSZ*NGEN, SEQ]
    const int*   gidx[8];  // 8 gold index arrays [TGOLD]
};

// ---------------------------------------------------------------------------
// helpers
// ---------------------------------------------------------------------------
__device__ __forceinline__ unsigned smem_u32(const void* p) {
    unsigned a;
    asm("{ .reg .u64 t; cvta.to.shared.u64 t, %1; cvt.u32.u64 %0, t; }"
        : "=r"(a) : "l"(p));
    return a;
}
__device__ __forceinline__ void cp_async16(unsigned dst, const float* src) {
    asm volatile("cp.async.cg.shared.global [%0], [%1], 16;" :: "r"(dst), "l"(src));
}
__device__ __forceinline__ unsigned fkey(float x) {
    int b = __float_as_int(x);
    return (unsigned)(b ^ ((b >> 31) | 0x80000000));
}
__device__ __forceinline__ float funkey(unsigned k) {
    int b = (k & 0x80000000u) ? (int)(k ^ 0x80000000u) : (int)(~k);
    return __int_as_float(b);
}
__device__ __forceinline__ unsigned redux_min_u32(unsigned x) {
    unsigned r;
    asm volatile("redux.sync.min.u32 %0, %1, 0xffffffff;" : "=r"(r) : "r"(x));
    return r;
}

// ---------------------------------------------------------------------------
// Cost kernel: one block per TWO (b,n) rows, 256 threads.
// THREE smem stages (24.6 KB -> 8 blocks/SM, 100% occupancy), depth-2
// cp.async pipeline; iteration k = (dist k>>1, row k&1); gold-index int4
// loaded once per dist and reused across both rows; exp at use site (no
// probs STS); ONE __syncthreads per iteration. Arithmetic identical to R9
// (bit-identical cost output).
// ---------------------------------------------------------------------------
__global__ __launch_bounds__(256)
void cost_kernel(const float* __restrict__ prel, const int* __restrict__ grel,
                 Ptrs ptrs, float* __restrict__ out) {
    const int row0 = blockIdx.x * 2;
    const int tid  = threadIdx.x;
    const int w    = tid >> 5;
    const int lane = tid & 31;

    __shared__ float stage[3][SEQ];       // 24 KB (raw logits)
    __shared__ float relp[2][32];
    __shared__ float red[2][8];

    const unsigned sbase = smem_u32(&stage[0][0]);

    // prologue: iterations 0,1 in flight (depth-2)
    #pragma unroll
    for (int k = 0; k < 2; k++) {
        const float* src = ptrs.pos[k >> 1] + (size_t)(row0 + (k & 1)) * SEQ;
        unsigned dst = sbase + (unsigned)(k * (SEQ * 4)) + (unsigned)(tid * 16);
        cp_async16(dst, src + 4 * tid);
        cp_async16(dst + 4096, src + 1024 + 4 * tid);
        asm volatile("cp.async.commit_group;");
    }

    // rel-class softmax: warp 0 -> row0, warp 1 -> row0+1 (overlaps loads)
    if (tid < 64) {
        float e = (lane < NCLS) ? __expf(prel[(size_t)(row0 + w) * NCLS + lane]) : 0.f;
        float s = e;
        #pragma unroll
        for (int o = 16; o; o >>= 1) s += __shfl_xor_sync(0xffffffffu, s, o);
        if (lane < NCLS) relp[w][lane] = e / s;
    }
    __syncthreads();

    const int4 gr = ((const int4*)grel)[tid];
    float acc[2][4];
    #pragma unroll
    for (int r = 0; r < 2; r++) {
        acc[r][0] = relp[r][gr.x];
        acc[r][1] = relp[r][gr.y];
        acc[r][2] = relp[r][gr.z];
        acc[r][3] = relp[r][gr.w];
    }

    int4 gi;
    #pragma unroll
    for (int k = 0; k < NITER; k++) {
        const int d  = k >> 1;
        const int r  = k & 1;
        const int sb = k % 3;
        const int pb = k & 1;

        // wait for MY copies of iteration k (k+1 may still be in flight)
        if (k < 15) asm volatile("cp.async.wait_group 1;");
        else        asm volatile("cp.async.wait_group 0;");

        // gather indices: load once per dist, reuse for the second row
        if (r == 0) gi = ((const int4*)ptrs.gidx[d])[tid];

        // sum of exps over this thread's own staged elements (raw kept)
        const float4* sp = (const float4*)&stage[sb][0];
        float4 x0 = sp[tid];
        float4 x1 = sp[tid + 256];
        float lsum = (__expf(x0.x) + __expf(x0.y)) + (__expf(x0.z) + __expf(x0.w))
                   + (__expf(x1.x) + __expf(x1.y)) + (__expf(x1.z) + __expf(x1.w));
        #pragma unroll
        for (int o = 16; o; o >>= 1) lsum += __shfl_xor_sync(0xffffffffu, lsum, o);
        if (lane == 0) red[pb][w] = lsum;
        __syncthreads();     // (a) red visible (b) all cp.asyncs of iter k
                             // published (c) gathers of k-1 ordered before
                             // the k+2 refill below (same stage slot)

        float s = ((red[pb][0] + red[pb][1]) + (red[pb][2] + red[pb][3]))
                + ((red[pb][4] + red[pb][5]) + (red[pb][6] + red[pb][7]));
        float inv = 1.0f / s;

        acc[r][0] += __expf(stage[sb][gi.x]) * inv;
        acc[r][1] += __expf(stage[sb][gi.y]) * inv;
        acc[r][2] += __expf(stage[sb][gi.z]) * inv;
        acc[r][3] += __expf(stage[sb][gi.w]) * inv;

        // refill: iteration k+2 into stage (k+2)%3
        if (k + 2 < NITER) {
            const int kn = k + 2;
            const float* src = ptrs.pos[kn >> 1] + (size_t)(row0 + (kn & 1)) * SEQ;
            unsigned dst = sbase + (unsigned)((kn % 3) * (SEQ * 4))
                                 + (unsigned)(tid * 16);
            cp_async16(dst, src + 4 * tid);
            cp_async16(dst + 4096, src + 1024 + 4 * tid);
            asm volatile("cp.async.commit_group;");
        }
    }

    #pragma unroll
    for (int r = 0; r < 2; r++) {
        float4 res = make_float4(-acc[r][0], -acc[r][1], -acc[r][2], -acc[r][3]);
        ((float4*)(out + (size_t)(row0 + r) * TGOLD))[tid] = res;
    }
}

// ---------------------------------------------------------------------------
// LSA: one warp per example. LAPJV, f32, register-resident dist/pred/v/y
// (validated identical assignment to the f64 reference — unique LP optimum).
// v zero-init -> rectangular dual feasibility. Argmin: monotone u32 key +
// 2x redux.min, smallest-j tie-break. C[i][j] = cost[b, j, b*G + i].
// ---------------------------------------------------------------------------
__global__ __launch_bounds__(32)
void lsa_kernel(const float* __restrict__ cost, float* __restrict__ rows_out,
                float* __restrict__ cols_out) {
    const int b = blockIdx.x;
    const int lane = threadIdx.x;

    __shared__ float Cf[G * NGEN];   // 8 KB
    __shared__ int   x[G];           // row -> col

    for (int j = lane; j < NGEN; j += 32) {
        const float4* src = (const float4*)(cost + ((size_t)(b * NGEN + j)) * TGOLD + b * G);
        #pragma unroll
        for (int q = 0; q < 4; q++) {
            float4 f = src[q];
            Cf[(q * 4 + 0) * NGEN + j] = f.x;
            Cf[(q * 4 + 1) * NGEN + j] = f.y;
            Cf[(q * 4 + 2) * NGEN + j] = f.z;
            Cf[(q * 4 + 3) * NGEN + j] = f.w;
        }
    }
    __syncwarp();

    float vreg[4];                 // v[j], j = lane + 32*t (ZERO init)
    int   yreg[4];                 // col -> row (-1 free)
    #pragma unroll
    for (int t = 0; t < 4; t++) { vreg[t] = 0.f; yreg[t] = -1; }

    for (int f = 0; f < G; f++) {
        float dreg[4];
        int   pr[4];
        #pragma unroll
        for (int t = 0; t < 4; t++) {
            dreg[t] = Cf[f * NGEN + lane + 32 * t] - vreg[t];
            pr[t] = f;
        }
        unsigned scan = 0;
        int jmin;
        float mu;

        while (true) {
            unsigned bestk = 0xFFFFFFFFu;
            unsigned bestj = 0xFFFFFFFFu;
            #pragma unroll
            for (int t = 0; t < 4; t++) {
                if (!((scan >> t) & 1u)) {
                    unsigned k = fkey(dreg[t]);
                    if (k < bestk) { bestk = k; bestj = (unsigned)(lane + 32 * t); }
                }
            }
            unsigned kmin = redux_min_u32(bestk);
            unsigned j1   = redux_min_u32((bestk == kmin) ? bestj : 0xFFFFFFFFu);
            mu   = funkey(kmin);
            jmin = (int)j1;

            const int tt = jmin >> 5, sl = jmin & 31;
            if (sl == lane) scan |= 1u << tt;

            int   ysel = (tt == 0) ? yreg[0] : (tt == 1) ? yreg[1]
                       : (tt == 2) ? yreg[2] : yreg[3];
            float vsel = (tt == 0) ? vreg[0] : (tt == 1) ? vreg[1]
                       : (tt == 2) ? vreg[2] : vreg[3];
            int   i1 = __shfl_sync(0xffffffffu, ysel, sl);
            float vj = __shfl_sync(0xffffffffu, vsel, sl);
            if (i1 < 0) break;

            float ui = Cf[i1 * NGEN + jmin] - vj;

            #pragma unroll
            for (int t = 0; t < 4; t++) {
                if (!((scan >> t) & 1u)) {
                    int j = lane + 32 * t;
                    float nd = mu + (Cf[i1 * NGEN + j] - vreg[t]) - ui;
                    if (nd < dreg[t]) { dreg[t] = nd; pr[t] = i1; }
                }
            }
        }

        // deferred potential update over scanned columns
        #pragma unroll
        for (int t = 0; t < 4; t++)
            if ((scan >> t) & 1u) vreg[t] += dreg[t] - mu;

        // augment along pred chain
        int j = jmin;
        while (true) {
            const int tt = j >> 5, sl = j & 31;
            int psel = (tt == 0) ? pr[0] : (tt == 1) ? pr[1]
                     : (tt == 2) ? pr[2] : pr[3];
            int i = __shfl_sync(0xffffffffu, psel, sl);
            if ((j & 31) == lane) yreg[j >> 5] = i;   // y[j] = i
            int jn = 0;
            if (lane == 0) {
                jn = (i == f) ? -1 : x[i];
                x[i] = j;
            }
            jn = __shfl_sync(0xffffffffu, jn, 0);
            if (i == f) break;
            j = jn;
        }
        __syncwarp();
    }

    // transposed return: col[i] = x[i]; order = argsort(col)
    if (lane < G) {
        int c = x[lane];
        int rank = 0;
        #pragma unroll
        for (int r2 = 0; r2 < G; r2++) rank += (x[r2] < c) ? 1 : 0;
        rows_out[b * G + rank] = (float)c;
        cols_out[b * G + rank] = (float)lane;
    }
}

// ---------------------------------------------------------------------------
// Launch
// ---------------------------------------------------------------------------
extern "C" void kernel_launch(void* const* d_in, const int* in_sizes, int n_in,
                              void* d_out, int out_size) {
    const float* prel = (const float*)d_in[0];
    Ptrs ptrs;
    for (int d = 0; d < 8; d++) ptrs.pos[d]  = (const float*)d_in[1 + d];
    const int* grel = (const int*)d_in[9];
    for (int d = 0; d < 8; d++) ptrs.gidx[d] = (const int*)d_in[10 + d];

    float* out = (float*)d_out;

    cost_kernel<<<(BSZ * NGEN) / 2, 256>>>(prel, grel, ptrs, out);

    float* rows_out = out + COST_ELEMS;
    float* cols_out = rows_out + (size_t)BSZ * G;
    lsa_kernel<<<BSZ, 32>>>(out, rows_out, cols_out);
}